// round 16
// baseline (speedup 1.0000x reference)
#include <cuda_runtime.h>
#include <cuda_fp16.h>
#include <cstdint>
#include <cstddef>

// ============================================================================
// TT-Linear, fp16 HMMA, fully fused (R15): x conversion AND both GEMM stages
// in one kernel; z never touches DRAM, XT intermediate eliminated.
//
//   stage1: z_b[m̂=512][i34=64] = G01(512x64) @ x_b^T   (K=64)   -> SMEM
//   stage2: y_b[o12=64][o34=64] = ẑ_b @ G23(512x64) + bias (K=512)
//   m̂ = r2*64 + o12; stage1 accumulators ARE stage2 A-fragments.
//
// Per row: x fp32 LDG->regs (coalesced) -> pad-65 SMEM staging -> fragment-
// order fp16 sX (exact splitXT math), overlapped with stage2 of prior row.
// DRAM: 64MB x in + 67MB y out only.
// SMEM: G01 64K + G23 64K + z 64K + sX 8K + staging 16.6K = 216.3KB.
// ============================================================================

//  g_A : [mrb=32][ks=4][lane=32][4 words: a0,a1,a2,a3]           (fp16x2)
//  g_B : [ks=32][nbp=4][lane=32][4 words: nb0{b0,b1}, nb1{b0,b1}]
__device__ __align__(16) uint32_t g_A[16384];
__device__ __align__(16) uint32_t g_B[16384];

// ---------------------------------------------------------------- helpers
__device__ __forceinline__ uint32_t pack_h2(float a, float b) {
    uint32_t r;
    asm("cvt.rn.f16x2.f32 %0, %1, %2;" : "=r"(r) : "f"(b), "f"(a));
    return r;
}
__device__ __forceinline__ void mma16816(float* c, const uint32_t* a,
                                         const uint32_t* b) {
    asm volatile(
        "mma.sync.aligned.m16n8k16.row.col.f32.f16.f16.f32 "
        "{%0,%1,%2,%3}, {%4,%5,%6,%7}, {%8,%9}, {%0,%1,%2,%3};"
        : "+f"(c[0]), "+f"(c[1]), "+f"(c[2]), "+f"(c[3])
        : "r"(a[0]), "r"(a[1]), "r"(a[2]), "r"(a[3]), "r"(b[0]), "r"(b[1]));
}
__device__ __forceinline__ uint32_t smaddr(const void* p) {
    return (uint32_t)__cvta_generic_to_shared(p);
}
__device__ __forceinline__ void cpa16(uint32_t dst_smem, const void* src) {
    asm volatile("cp.async.cg.shared.global [%0], [%1], 16;"
                 :: "r"(dst_smem), "l"(src) : "memory");
}
__device__ __forceinline__ void cpa_commit() {
    asm volatile("cp.async.commit_group;" ::: "memory");
}
__device__ __forceinline__ void cpa_wait0() {
    asm volatile("cp.async.wait_group 0;" ::: "memory");
}

// ---------------------------------------------------------------------------
// prep: merge core pairs into fp16 fragment-order words (m̂ = r2*64+o12).
// ---------------------------------------------------------------------------
__global__ void k_prep(const float* __restrict__ c0, const float* __restrict__ c1,
                       const float* __restrict__ c2, const float* __restrict__ c3) {
    int t = blockIdx.x * blockDim.x + threadIdx.x;  // 0..32767
    if (t < 16384) {
        int w2 = t & 3, lane = (t >> 2) & 31, ks = (t >> 7) & 3, mrb = t >> 9;
        int g = lane >> 2, t4 = lane & 3;
        int mhat = mrb * 16 + (w2 & 1) * 8 + g;
        int k0 = ks * 16 + ((w2 >> 1) & 1) * 8 + t4 * 2;
        int r2 = mhat >> 6, o12 = mhat & 63;
        int o1 = o12 >> 3, o2 = o12 & 7;
        float s[2];
#pragma unroll
        for (int d = 0; d < 2; ++d) {
            int k = k0 + d;
            int i1 = k >> 3, i2 = k & 7;
            float acc = 0.0f;
#pragma unroll
            for (int r1 = 0; r1 < 8; ++r1)
                acc += c0[(i1 * 8 + o1) * 8 + r1] *
                       c1[((r1 * 8 + i2) * 8 + o2) * 8 + r2];
            s[d] = acc;
        }
        g_A[t] = pack_h2(s[0], s[1]);
    } else {
        int u = t - 16384;
        int w = u & 3, lane = (u >> 2) & 31, nbp = (u >> 7) & 3, ks = u >> 9;
        int g = lane >> 2, t4 = lane & 3;
        int nb = nbp * 2 + (w >> 1);
        int n  = nb * 8 + g;
        int k0 = ks * 16 + (w & 1) * 8 + t4 * 2;
        int o3 = n >> 3, o4 = n & 7;
        float s[2];
#pragma unroll
        for (int d = 0; d < 2; ++d) {
            int k2v = k0 + d;
            int r2 = k2v >> 6, i3 = (k2v >> 3) & 7, i4 = k2v & 7;
            float acc = 0.0f;
#pragma unroll
            for (int r3 = 0; r3 < 8; ++r3)
                acc += c2[((r2 * 8 + i3) * 8 + o3) * 8 + r3] *
                       c3[(r3 * 8 + i4) * 8 + o4];
            s[d] = acc;
        }
        g_B[u] = pack_h2(s[0], s[1]);
    }
}

// ---------------------------------------------------------------------------
// fused: 4 batch rows per CTA. Per row: convert x (regs->staging->sX),
// stage1 -> SMEM z -> stage2 -> out.
// SMEM words: sG01[0,16384) sG23[16384,32768) sZ[32768,49152)
//             sX[49152,51200) sxf(fp32)[51200,55360)
// ---------------------------------------------------------------------------
__global__ __launch_bounds__(512, 1) void k_fused(const float* __restrict__ x,
                                                  const float* __restrict__ bias,
                                                  float* __restrict__ out) {
    extern __shared__ uint32_t sm[];
    uint32_t* sG01 = sm;             // 16384 words
    uint32_t* sG23 = sm + 16384;     // 16384 words
    uint32_t* sZ   = sm + 32768;     // 16384 words
    uint32_t* sX   = sm + 49152;     // 2048 words (single buffer)
    float*    sxf  = (float*)(sm + 51200);  // 64*65 = 4160 floats
    const int tid = threadIdx.x;
    const int lane = tid & 31, w = tid >> 5;
    const int g = lane >> 2, t4 = lane & 3;
    const int b0 = blockIdx.x * 4;

    // ---- helper lambdas (inlined) ----
    // stage x registers -> pad-65 fp32 staging (exact splitXT store pattern)
#define STAGE_RX(rxa, rxb) do {                                               \
        int i12a = tid >> 4, ca = (tid & 15) * 4;                             \
        float* da = &sxf[i12a * 65 + ca];                                     \
        da[0] = (rxa).x; da[1] = (rxa).y; da[2] = (rxa).z; da[3] = (rxa).w;   \
        float* db = &sxf[(i12a + 32) * 65 + ca];                              \
        db[0] = (rxb).x; db[1] = (rxb).y; db[2] = (rxb).z; db[3] = (rxb).w;   \
    } while (0)
    // convert staging -> fragment-order sX (exact splitXT math, 512 thr)
#define CONVERT_X() do {                                                      \
        _Pragma("unroll")                                                     \
        for (int it = 0; it < 4; ++it) {                                      \
            int widx = it * 512 + tid;                                        \
            int ww = widx & 3, fl = (widx >> 2) & 31;                         \
            int nbp = (widx >> 7) & 3, ks = widx >> 9;                        \
            int fg = fl >> 2, ft4 = fl & 3;                                   \
            int nb = nbp * 2 + (ww >> 1);                                     \
            int i34 = nb * 8 + fg;                                            \
            int k0 = ks * 16 + (ww & 1) * 8 + ft4 * 2;                        \
            sX[widx] = pack_h2(sxf[k0 * 65 + i34], sxf[(k0 + 1) * 65 + i34]); \
        }                                                                     \
    } while (0)

    // ---- prologue ----
    float4 rx0, rx1;
    {   // x row b0 -> regs
        const float4* srcX = (const float4*)(x + (size_t)b0 * 4096);
        rx0 = srcX[tid]; rx1 = srcX[tid + 512];
    }
    {   // weights via cp.async (one group)
        const uint4* srcA = (const uint4*)g_A;
        const uint4* srcB = (const uint4*)g_B;
#pragma unroll
        for (int p = 0; p < 8; ++p) {
            int j = tid + 512 * p;
            cpa16(smaddr(&sG01[j * 4]), &srcA[j]);
            cpa16(smaddr(&sG23[j * 4]), &srcB[j]);
        }
        cpa_commit();
    }
    STAGE_RX(rx0, rx1);
    __syncthreads();          // staging(row0) published
    CONVERT_X();              // sX <- row 0
    {   // x row b0+1 -> regs
        const float4* srcX = (const float4*)(x + (size_t)(b0 + 1) * 4096);
        rx0 = srcX[tid]; rx1 = srcX[tid + 512];
    }
    cpa_wait0();              // weights resident
    __syncthreads();          // publish sX(row0) + weights

    const int mt2 = w >> 2, nbp2 = w & 3;  // stage2 warp mapping

    for (int r = 0; r < 4; ++r) {
        // ---------------- stage 1: z = G01 @ x_r^T ----------------
        float acc1[2][8][4];
#pragma unroll
        for (int a = 0; a < 2; ++a)
#pragma unroll
            for (int b_ = 0; b_ < 8; ++b_)
#pragma unroll
                for (int q = 0; q < 4; ++q) acc1[a][b_][q] = 0.0f;

#pragma unroll
        for (int ks = 0; ks < 4; ++ks) {
            uint4 AQ[2];
#pragma unroll
            for (int mt = 0; mt < 2; ++mt)
                AQ[mt] = *(const uint4*)&sG01[(((w * 2 + mt) * 4 + ks) * 32 + lane) * 4];
#pragma unroll
            for (int nbp = 0; nbp < 4; ++nbp) {
                uint4 BQ = *(const uint4*)&sX[((ks * 4 + nbp) * 32 + lane) * 4];
#pragma unroll
                for (int mt = 0; mt < 2; ++mt) {
                    mma16816(acc1[mt][2 * nbp],     (const uint32_t*)&AQ[mt], &BQ.x);
                    mma16816(acc1[mt][2 * nbp + 1], (const uint32_t*)&AQ[mt], &BQ.z);
                }
            }
        }
        // STS z fragments (proven R13/R14 layout)
#pragma unroll
        for (int mt = 0; mt < 2; ++mt) {
            int Rb_rel = (w & 1) * 2 + mt;
#pragma unroll
            for (int np = 0; np < 4; ++np) {
                int ks2 = (w >> 1) * 4 + np;
                uint32_t idx = (uint32_t)((Rb_rel * 32 + ks2) * 32 + lane) * 4;
                const float* A0 = acc1[mt][2 * np];
                const float* A1 = acc1[mt][2 * np + 1];
                uint4 v;
                v.x = pack_h2(A0[0], A0[1]);
                v.y = pack_h2(A0[2], A0[3]);
                v.z = pack_h2(A1[0], A1[1]);
                v.w = pack_h2(A1[2], A1[3]);
                *(uint4*)&sZ[idx] = v;
            }
        }
        __syncthreads();   // (b) publish sZ; stage1 reads of sX/sxf done

        // stage x row r+1 into staging; issue LDG for row r+2
        if (r < 3) STAGE_RX(rx0, rx1);
        if (r < 2) {
            const float4* srcX = (const float4*)(x + (size_t)(b0 + r + 2) * 4096);
            rx0 = srcX[tid]; rx1 = srcX[tid + 512];
        }

        // ---------------- stage 2: y_r = ẑ @ G23 + bias ----------------
        float acc2[2][4];
#pragma unroll
        for (int j = 0; j < 2; ++j)
#pragma unroll
            for (int q = 0; q < 4; ++q) acc2[j][q] = 0.0f;

#pragma unroll 8
        for (int ks = 0; ks < 32; ++ks) {
            uint4 AQ = *(const uint4*)&sZ[((mt2 * 32 + ks) * 32 + lane) * 4];
            uint4 BQ = *(const uint4*)&sG23[((ks * 4 + nbp2) * 32 + lane) * 4];
            mma16816(acc2[0], (const uint32_t*)&AQ, &BQ.x);
            mma16816(acc2[1], (const uint32_t*)&AQ, &BQ.z);
        }

        const int b = b0 + r;
#pragma unroll
        for (int j = 0; j < 2; ++j) {
            int nb = nbp2 * 2 + j;
            int col = nb * 8 + t4 * 2;
            int o12a = mt2 * 16 + g;
            float2 bva = __ldg((const float2*)&bias[o12a * 64 + col]);
            float2 va;
            va.x = acc2[j][0] + bva.x;
            va.y = acc2[j][1] + bva.y;
            *(float2*)&out[((size_t)b * 64 + o12a) * 64 + col] = va;
            int o12b = o12a + 8;
            float2 bvb = __ldg((const float2*)&bias[o12b * 64 + col]);
            float2 vb;
            vb.x = acc2[j][2] + bvb.x;
            vb.y = acc2[j][3] + bvb.y;
            *(float2*)&out[((size_t)b * 64 + o12b) * 64 + col] = vb;
        }

        if (r < 3) {
            __syncthreads();   // (c) publish staging(row r+1); sZ readers done
            CONVERT_X();       // sX <- row r+1
            __syncthreads();   // (a) publish sX; sZ free for stage1(r+1)
        }
    }
#undef STAGE_RX
#undef CONVERT_X
}

// ---------------------------------------------------------------------------
extern "C" void kernel_launch(void* const* d_in, const int* in_sizes, int n_in,
                              void* d_out, int out_size) {
    (void)in_sizes; (void)n_in; (void)out_size;
    const float* x    = (const float*)d_in[0];
    const float* c0   = (const float*)d_in[1];
    const float* c1   = (const float*)d_in[2];
    const float* c2   = (const float*)d_in[3];
    const float* c3   = (const float*)d_in[4];
    const float* bias = (const float*)d_in[5];
    float* out = (float*)d_out;

    cudaFuncSetAttribute(k_fused, cudaFuncAttributeMaxDynamicSharedMemorySize,
                         221440);

    k_prep<<<128, 256>>>(c0, c1, c2, c3);
    k_fused<<<1024, 512, 221440>>>(x, bias, out);  // x->z->y, all in-SMEM
}